// round 15
// baseline (speedup 1.0000x reference)
#include <cuda_runtime.h>

#define N   512
#define DIM 384
#define BK  32
#define NTL 12          // DIM / BK

// Scratch (device globals per allocation-free rule)
__device__ float    g_D[N * N];    // pairwise distances, diag = 1e6
__device__ float    g_prec[N];     // per-query soft precision
__device__ unsigned g_ctr1;        // monotonic ticket: grid barrier (replay-safe)
__device__ unsigned g_ctr2;        // monotonic ticket: completion count

// Branchless full-range sigmoid (exp underflow -> exact 0/1 saturation)
__device__ __forceinline__ float sigmoid_nb(float x) {
    float e = __expf(-fabsf(x));
    float p = __fdividef(1.f, 1.f + e);
    return (x >= 0.f) ? p : 1.f - p;
}

#define SA_STR 34   // 136 B rows (8B-aligned for LDS.64)
#define SB_STR 66   // 264 B rows
// phase1: sa 2*32*34=2176 | sb 2*32*66=4224  -> 6400 floats
// phase2 aliases: sd 4*512=2048 | slab 512   -> 2560 floats
#define SMEM_FLOATS 6400

__global__ void __launch_bounds__(512, 1)
k_fused(const float* __restrict__ emb, const int* __restrict__ labels,
        float* __restrict__ out)
{
    __shared__ __align__(16) float smem[SMEM_FLOATS];
    __shared__ float snA[32];
    __shared__ float snB[64];
    __shared__ float wnum[16];
    __shared__ int   wcnt[16];
    __shared__ float swr[16];
    __shared__ int   s_done;

    const int t = threadIdx.x;
    const int b = blockIdx.x;

    // ================= Phase 1: Gram -> distance tile, 2x2 micro, 16 warps =================
    {
        float* sa0 = smem;                    // [2][32][SA_STR]
        float* sb0 = smem + 2 * BK * SA_STR;  // [2][32][SB_STR]

        const int q0 = (b >> 3) * 32;
        const int m0 = (b & 7) * 64;
        const int ty = t >> 5;        // warp id 0..15 -> q-rows 2ty, 2ty+1
        const int tx = t & 31;        // m-col pair 2tx
        const int arow = t >> 3;      // A loader (t<256): rows 0..31
        const int ac4  = t & 7;       // k-chunk (float4)
        const bool isA = (t < 256);

        const float* pa = emb + (size_t)(q0 + (arow & 31)) * DIM + ac4 * 4;
        const float* pb = emb + (size_t)(m0 + arow) * DIM + ac4 * 4;   // rows 0..63

        float a00 = 0.f, a01 = 0.f, a10 = 0.f, a11 = 0.f;
        float nA = 0.f, nB = 0.f;

        float4 ra, rb;
        if (isA) ra = *(const float4*)pa;
        rb = *(const float4*)pb;

        // store tile 0 into buffer 0 (k-major transpose)
        if (isA) {
#pragma unroll
            for (int e = 0; e < 4; e++)
                sa0[(ac4 * 4 + e) * SA_STR + arow] = ((const float*)&ra)[e];
            nA = fmaf(ra.x,ra.x,fmaf(ra.y,ra.y,fmaf(ra.z,ra.z,fmaf(ra.w,ra.w,nA))));
        }
#pragma unroll
        for (int e = 0; e < 4; e++)
            sb0[(ac4 * 4 + e) * SB_STR + arow] = ((const float*)&rb)[e];
        nB = fmaf(rb.x,rb.x,fmaf(rb.y,rb.y,fmaf(rb.z,rb.z,fmaf(rb.w,rb.w,nB))));
        __syncthreads();

#pragma unroll 1
        for (int tt = 0; tt < NTL; tt++) {
            const int cur = tt & 1;
            const float* csa = sa0 + cur * BK * SA_STR;
            const float* csb = sb0 + cur * BK * SB_STR;

            if (tt + 1 < NTL) {   // prefetch next tile into registers
                const int ko = (tt + 1) * BK;
                if (isA) ra = *(const float4*)(pa + ko);
                rb = *(const float4*)(pb + ko);
            }

#pragma unroll
            for (int k = 0; k < BK; k++) {
                float2 av = *(const float2*)&csa[k * SA_STR + 2 * ty];
                float2 bv = *(const float2*)&csb[k * SB_STR + 2 * tx];
                a00 = fmaf(av.x, bv.x, a00);
                a01 = fmaf(av.x, bv.y, a01);
                a10 = fmaf(av.y, bv.x, a10);
                a11 = fmaf(av.y, bv.y, a11);
            }

            if (tt + 1 < NTL) {   // store prefetched tile into the other buffer
                float* nsa = sa0 + (cur ^ 1) * BK * SA_STR;
                float* nsb = sb0 + (cur ^ 1) * BK * SB_STR;
                if (isA) {
#pragma unroll
                    for (int e = 0; e < 4; e++)
                        nsa[(ac4 * 4 + e) * SA_STR + arow] = ((const float*)&ra)[e];
                    nA = fmaf(ra.x,ra.x,fmaf(ra.y,ra.y,fmaf(ra.z,ra.z,fmaf(ra.w,ra.w,nA))));
                }
#pragma unroll
                for (int e = 0; e < 4; e++)
                    nsb[(ac4 * 4 + e) * SB_STR + arow] = ((const float*)&rb)[e];
                nB = fmaf(rb.x,rb.x,fmaf(rb.y,rb.y,fmaf(rb.z,rb.z,fmaf(rb.w,rb.w,nB))));
                __syncthreads();
            }
        }

        // row norms: 8 k-chunk threads per row share t>>3 -> xor 1,2,4 in-warp
        nA += __shfl_xor_sync(0xffffffffu, nA, 1);
        nA += __shfl_xor_sync(0xffffffffu, nA, 2);
        nA += __shfl_xor_sync(0xffffffffu, nA, 4);
        nB += __shfl_xor_sync(0xffffffffu, nB, 1);
        nB += __shfl_xor_sync(0xffffffffu, nB, 2);
        nB += __shfl_xor_sync(0xffffffffu, nB, 4);
        __syncthreads();
        if (ac4 == 0) {
            if (isA) snA[arow] = nA;
            snB[arow] = nB;
        }
        __syncthreads();

        // epilogue: distances, diag = 1e6 (float2 stores, coalesced across tx)
        const int mc = m0 + 2 * tx;
#pragma unroll
        for (int i = 0; i < 2; i++) {
            const int q = q0 + 2 * ty + i;
            const float nq = snA[2 * ty + i];
            float acx = (i == 0) ? a00 : a10;
            float acy = (i == 0) ? a01 : a11;
            float d0 = nq + snB[2 * tx]     - 2.f * acx;
            float d1 = nq + snB[2 * tx + 1] - 2.f * acy;
            float v0 = (q == mc)     ? 1e6f : sqrtf(fmaxf(d0, 1e-12f));
            float v1 = (q == mc + 1) ? 1e6f : sqrtf(fmaxf(d1, 1e-12f));
            *(float2*)&g_D[(size_t)q * N + mc] = make_float2(v0, v1);
        }
    }

    // ================= Grid barrier (replay-safe monotonic ticket, R7-proven) =================
    __syncthreads();
    if (t == 0) {
        __threadfence();
        unsigned tk = atomicAdd(&g_ctr1, 1u);
        unsigned target = (tk / 128u) * 128u + 128u;
        while (atomicAdd(&g_ctr1, 0u) < target) __nanosleep(32);
        __threadfence();
    }
    __syncthreads();

    // ================= Phase 2: soft precision (R13-proven, 512 threads) =================
    {
        float* sd   = smem;                   // 4 rows x 512
        int*   slab = (int*)(smem + 4 * N);   // 512 labels

        const int lane = t & 31;
        const int w    = t >> 5;
        const int q0b  = b * 4;

        ((float4*)sd)[t] = __ldcg(&((const float4*)(g_D + (size_t)q0b * N))[t]);
        if (t < 128) ((int4*)slab)[t] = ((const int4*)labels)[t];
        __syncthreads();

        const int   qsel = w & 3;
        const int   q    = q0b + qsel;
        const int   lq   = slab[q];
        const float* row = sd + qsel * N;
        const int   jb   = (w >> 2) * 128;

        float num = 0.f;
        int   cnt = 0;
#pragma unroll
        for (int c = 0; c < 4; c++) {
            int j = jb + c * 32 + lane;
            bool f = (j != q) && (slab[j] == lq);
            unsigned bm = __ballot_sync(0xffffffffu, f);
            cnt += __popc(bm);
            while (bm) {                      // ascending j: deterministic
                int bit = __ffs(bm) - 1;
                bm &= bm - 1;
                float dj = row[jb + c * 32 + bit];
                float part = 0.f;
#pragma unroll
                for (int i = 0; i < 16; i++)
                    part += sigmoid_nb((dj - row[lane + 32 * i]) * 100.0f); // 1/T2
#pragma unroll
                for (int o = 16; o; o >>= 1)
                    part += __shfl_xor_sync(0xffffffffu, part, o);
                num += sigmoid_nb(5.0f - part);   // K=5, T1=1
            }
        }
        if (lane == 0) { wnum[w] = num; wcnt[w] = cnt; }
        __syncthreads();

        if (t < 4) {
            float s = wnum[t] + wnum[4 + t] + wnum[8 + t] + wnum[12 + t];
            int   c = wcnt[t] + wcnt[4 + t] + wcnt[8 + t] + wcnt[12 + t];
            g_prec[q0b + t] = s / fminf((float)c, 5.0f);  // 0/0 -> NaN like reference
        }
    }

    // ================= Phase 3: last-arriving block does the fixed-order mean =================
    __syncthreads();
    if (t == 0) {
        __threadfence();
        unsigned tk = atomicAdd(&g_ctr2, 1u);
        s_done = ((tk & 127u) == 127u) ? 1 : 0;
    }
    __syncthreads();

    if (s_done) {
        __threadfence();
        const int lane = t & 31;
        const int w    = t >> 5;
        float v = __ldcg(&g_prec[t]);         // 512 threads, 512 values
#pragma unroll
        for (int o = 16; o; o >>= 1)
            v += __shfl_xor_sync(0xffffffffu, v, o);
        if (lane == 0) swr[w] = v;
        __syncthreads();
        if (t == 0) {
            float s = 0.f;
#pragma unroll
            for (int i = 0; i < 16; i++) s += swr[i];
            out[0] = 1.0f - s / (float)N;
        }
    }
}

extern "C" void kernel_launch(void* const* d_in, const int* in_sizes, int n_in,
                              void* d_out, int out_size) {
    const float* emb    = (const float*)d_in[0];
    const int*   labels = (const int*)d_in[1];
    k_fused<<<128, 512>>>(emb, labels, (float*)d_out);
}

// round 16
// speedup vs baseline: 1.1936x; 1.1936x over previous
#include <cuda_runtime.h>

#define N   512
#define DIM 384
#define BK  32
#define NTL 12          // DIM / BK

// Scratch (device globals per allocation-free rule)
__device__ float    g_D[N * N];    // pairwise distances, diag = 1e6
__device__ float    g_prec[N];     // per-query soft precision
__device__ unsigned g_ctr1;        // monotonic ticket: grid barrier (replay-safe)
__device__ unsigned g_ctr2;        // monotonic ticket: completion count

// Branchless full-range sigmoid (exp underflow -> exact 0/1 saturation)
__device__ __forceinline__ float sigmoid_nb(float x) {
    float e = __expf(-fabsf(x));
    float p = __fdividef(1.f, 1.f + e);
    return (x >= 0.f) ? p : 1.f - p;
}

#define SA_STR 36   // 144 B rows: 16B-aligned
#define SB_STR 68   // 272 B rows: 16B-aligned
// phase1: sa 2*32*36 = 2304 | sb 2*32*68 = 4352 -> 6656 floats (26.6 KB)
// phase2 aliases: sd 4*512 = 2048 | slab 512    -> 2560 floats
#define SMEM_FLOATS (2 * BK * SA_STR + 2 * BK * SB_STR)

__global__ void __launch_bounds__(512, 1)
k_fused(const float* __restrict__ emb, const int* __restrict__ labels,
        float* __restrict__ out)
{
    __shared__ __align__(16) float smem[SMEM_FLOATS];
    __shared__ float snA[32];
    __shared__ float snB[64];
    __shared__ float wnum[16];
    __shared__ int   wcnt[16];
    __shared__ float swr[16];
    __shared__ int   s_done;

    const int t = threadIdx.x;
    const int b = blockIdx.x;

    // ======== Phase 1: Gram -> distance tile (R13-proven 4x4 body, t<128 active) ========
    {
        float* sa = smem;                     // [2][BK*SA_STR]
        float* sb = smem + 2 * BK * SA_STR;   // [2][BK*SB_STR]

        const bool act = (t < 128);
        const int  u   = t & 127;
        const int  q0  = (b >> 3) * 32;
        const int  m0  = (b & 7) * 64;
        const int  ty  = u >> 4;       // 0..7  -> 4 q-rows at ty*4
        const int  tx  = u & 15;       // 0..15 -> 4 m-cols at tx*4
        const int  arow = u >> 3, ac4 = u & 7;

        const float* pa0 = emb + (size_t)(q0 + arow)      * DIM + ac4 * 4;
        const float* pa1 = emb + (size_t)(q0 + arow + 16) * DIM + ac4 * 4;
        const float* pb[4];
#pragma unroll
        for (int i = 0; i < 4; i++)
            pb[i] = emb + (size_t)(m0 + arow + 16 * i) * DIM + ac4 * 4;

        float acc[4][4];
#pragma unroll
        for (int i = 0; i < 4; i++)
#pragma unroll
            for (int j = 0; j < 4; j++) acc[i][j] = 0.f;
        float nA0 = 0.f, nA1 = 0.f;
        float nB[4] = {0.f, 0.f, 0.f, 0.f};
        float4 ra0 = {0,0,0,0}, ra1 = {0,0,0,0};
        float4 rb[4] = {{0,0,0,0},{0,0,0,0},{0,0,0,0},{0,0,0,0}};

        if (act) {
            ra0 = *(const float4*)pa0;
            ra1 = *(const float4*)pa1;
#pragma unroll
            for (int i = 0; i < 4; i++) rb[i] = *(const float4*)pb[i];
#pragma unroll
            for (int e = 0; e < 4; e++) {
                sa[(ac4 * 4 + e) * SA_STR + arow]      = ((const float*)&ra0)[e];
                sa[(ac4 * 4 + e) * SA_STR + arow + 16] = ((const float*)&ra1)[e];
#pragma unroll
                for (int i = 0; i < 4; i++)
                    sb[(ac4 * 4 + e) * SB_STR + arow + 16 * i] = ((const float*)&rb[i])[e];
            }
            nA0 = fmaf(ra0.x,ra0.x,fmaf(ra0.y,ra0.y,fmaf(ra0.z,ra0.z,fmaf(ra0.w,ra0.w,nA0))));
            nA1 = fmaf(ra1.x,ra1.x,fmaf(ra1.y,ra1.y,fmaf(ra1.z,ra1.z,fmaf(ra1.w,ra1.w,nA1))));
#pragma unroll
            for (int i = 0; i < 4; i++)
                nB[i] = fmaf(rb[i].x,rb[i].x,fmaf(rb[i].y,rb[i].y,fmaf(rb[i].z,rb[i].z,fmaf(rb[i].w,rb[i].w,nB[i]))));
        }
        __syncthreads();

#pragma unroll 1
        for (int tt = 0; tt < NTL; tt++) {
            const int cur = tt & 1;
            if (act) {
                if (tt + 1 < NTL) {   // prefetch next tile into registers
                    const int ko = (tt + 1) * BK;
                    ra0 = *(const float4*)(pa0 + ko);
                    ra1 = *(const float4*)(pa1 + ko);
#pragma unroll
                    for (int i = 0; i < 4; i++) rb[i] = *(const float4*)(pb[i] + ko);
                }
                const float* csa = sa + cur * BK * SA_STR;
                const float* csb = sb + cur * BK * SB_STR;
#pragma unroll
                for (int k = 0; k < BK; k++) {
                    float4 av = *(const float4*)&csa[k * SA_STR + ty * 4];
                    float4 bv = *(const float4*)&csb[k * SB_STR + tx * 4];
                    acc[0][0] = fmaf(av.x, bv.x, acc[0][0]);
                    acc[0][1] = fmaf(av.x, bv.y, acc[0][1]);
                    acc[0][2] = fmaf(av.x, bv.z, acc[0][2]);
                    acc[0][3] = fmaf(av.x, bv.w, acc[0][3]);
                    acc[1][0] = fmaf(av.y, bv.x, acc[1][0]);
                    acc[1][1] = fmaf(av.y, bv.y, acc[1][1]);
                    acc[1][2] = fmaf(av.y, bv.z, acc[1][2]);
                    acc[1][3] = fmaf(av.y, bv.w, acc[1][3]);
                    acc[2][0] = fmaf(av.z, bv.x, acc[2][0]);
                    acc[2][1] = fmaf(av.z, bv.y, acc[2][1]);
                    acc[2][2] = fmaf(av.z, bv.z, acc[2][2]);
                    acc[2][3] = fmaf(av.z, bv.w, acc[2][3]);
                    acc[3][0] = fmaf(av.w, bv.x, acc[3][0]);
                    acc[3][1] = fmaf(av.w, bv.y, acc[3][1]);
                    acc[3][2] = fmaf(av.w, bv.z, acc[3][2]);
                    acc[3][3] = fmaf(av.w, bv.w, acc[3][3]);
                }
                if (tt + 1 < NTL) {   // store prefetched tile into the other buffer
                    float* nsa = sa + (cur ^ 1) * BK * SA_STR;
                    float* nsb = sb + (cur ^ 1) * BK * SB_STR;
#pragma unroll
                    for (int e = 0; e < 4; e++) {
                        nsa[(ac4 * 4 + e) * SA_STR + arow]      = ((const float*)&ra0)[e];
                        nsa[(ac4 * 4 + e) * SA_STR + arow + 16] = ((const float*)&ra1)[e];
#pragma unroll
                        for (int i = 0; i < 4; i++)
                            nsb[(ac4 * 4 + e) * SB_STR + arow + 16 * i] = ((const float*)&rb[i])[e];
                    }
                    nA0 = fmaf(ra0.x,ra0.x,fmaf(ra0.y,ra0.y,fmaf(ra0.z,ra0.z,fmaf(ra0.w,ra0.w,nA0))));
                    nA1 = fmaf(ra1.x,ra1.x,fmaf(ra1.y,ra1.y,fmaf(ra1.z,ra1.z,fmaf(ra1.w,ra1.w,nA1))));
#pragma unroll
                    for (int i = 0; i < 4; i++)
                        nB[i] = fmaf(rb[i].x,rb[i].x,fmaf(rb[i].y,rb[i].y,fmaf(rb[i].z,rb[i].z,fmaf(rb[i].w,rb[i].w,nB[i]))));
                }
            }
            if (tt + 1 < NTL) __syncthreads();   // uniform condition: all threads
        }

        if (act) {
            nA0 += __shfl_xor_sync(0xffffffffu, nA0, 1);
            nA0 += __shfl_xor_sync(0xffffffffu, nA0, 2);
            nA0 += __shfl_xor_sync(0xffffffffu, nA0, 4);
            nA1 += __shfl_xor_sync(0xffffffffu, nA1, 1);
            nA1 += __shfl_xor_sync(0xffffffffu, nA1, 2);
            nA1 += __shfl_xor_sync(0xffffffffu, nA1, 4);
#pragma unroll
            for (int i = 0; i < 4; i++) {
                nB[i] += __shfl_xor_sync(0xffffffffu, nB[i], 1);
                nB[i] += __shfl_xor_sync(0xffffffffu, nB[i], 2);
                nB[i] += __shfl_xor_sync(0xffffffffu, nB[i], 4);
            }
            if (ac4 == 0) {
                snA[arow]      = nA0;
                snA[arow + 16] = nA1;
#pragma unroll
                for (int i = 0; i < 4; i++) snB[arow + 16 * i] = nB[i];
            }
        }
        __syncthreads();

        if (act) {
#pragma unroll
            for (int i = 0; i < 4; i++) {
                const int q  = q0 + ty * 4 + i;
                const int mb = m0 + tx * 4;
                const float nq = snA[ty * 4 + i];
                float dv[4];
#pragma unroll
                for (int c = 0; c < 4; c++) {
                    float d2 = nq + snB[tx * 4 + c] - 2.f * acc[i][c];
                    dv[c] = (q == mb + c) ? 1e6f : sqrtf(fmaxf(d2, 1e-12f));
                }
                *(float4*)&g_D[(size_t)q * N + mb] = make_float4(dv[0], dv[1], dv[2], dv[3]);
            }
        }
    }

    // ======== Grid barrier: monotonic ticket, LOAD-poll (no RMW contention) ========
    __syncthreads();
    if (t == 0) {
        __threadfence();
        unsigned tk = atomicAdd(&g_ctr1, 1u);          // single RMW per block
        unsigned target = (tk / 128u) * 128u + 128u;
        while (*(volatile unsigned*)&g_ctr1 < target)  // plain load: no serialization
            __nanosleep(64);
        __threadfence();
    }
    __syncthreads();

    // ======== Phase 2: soft precision (R13-proven, 512 threads, verbatim) ========
    {
        float* sd   = smem;                   // 4 rows x 512
        int*   slab = (int*)(smem + 4 * N);   // 512 labels

        const int lane = t & 31;
        const int w    = t >> 5;
        const int q0b  = b * 4;

        ((float4*)sd)[t] = __ldcg(&((const float4*)(g_D + (size_t)q0b * N))[t]);
        if (t < 128) ((int4*)slab)[t] = ((const int4*)labels)[t];
        __syncthreads();

        const int   qsel = w & 3;
        const int   q    = q0b + qsel;
        const int   lq   = slab[q];
        const float* row = sd + qsel * N;
        const int   jb   = (w >> 2) * 128;

        float num = 0.f;
        int   cnt = 0;
#pragma unroll
        for (int c = 0; c < 4; c++) {
            int j = jb + c * 32 + lane;
            bool f = (j != q) && (slab[j] == lq);
            unsigned bm = __ballot_sync(0xffffffffu, f);
            cnt += __popc(bm);
            while (bm) {                      // ascending j: deterministic
                int bit = __ffs(bm) - 1;
                bm &= bm - 1;
                float dj = row[jb + c * 32 + bit];
                float part = 0.f;
#pragma unroll
                for (int i = 0; i < 16; i++)
                    part += sigmoid_nb((dj - row[lane + 32 * i]) * 100.0f); // 1/T2
#pragma unroll
                for (int o = 16; o; o >>= 1)
                    part += __shfl_xor_sync(0xffffffffu, part, o);
                num += sigmoid_nb(5.0f - part);   // K=5, T1=1
            }
        }
        if (lane == 0) { wnum[w] = num; wcnt[w] = cnt; }
        __syncthreads();

        if (t < 4) {
            float s = wnum[t] + wnum[4 + t] + wnum[8 + t] + wnum[12 + t];
            int   c = wcnt[t] + wcnt[4 + t] + wcnt[8 + t] + wcnt[12 + t];
            g_prec[q0b + t] = s / fminf((float)c, 5.0f);  // 0/0 -> NaN like reference
        }
    }

    // ======== Phase 3: last-arriving block does the fixed-order mean ========
    __syncthreads();
    if (t == 0) {
        __threadfence();
        unsigned tk = atomicAdd(&g_ctr2, 1u);
        s_done = ((tk & 127u) == 127u) ? 1 : 0;
    }
    __syncthreads();

    if (s_done) {
        __threadfence();
        const int lane = t & 31;
        const int w    = t >> 5;
        float v = __ldcg(&g_prec[t]);         // 512 threads, 512 values
#pragma unroll
        for (int o = 16; o; o >>= 1)
            v += __shfl_xor_sync(0xffffffffu, v, o);
        if (lane == 0) swr[w] = v;
        __syncthreads();
        if (t == 0) {
            float s = 0.f;
#pragma unroll
            for (int i = 0; i < 16; i++) s += swr[i];
            out[0] = 1.0f - s / (float)N;
        }
    }
}

extern "C" void kernel_launch(void* const* d_in, const int* in_sizes, int n_in,
                              void* d_out, int out_size) {
    const float* emb    = (const float*)d_in[0];
    const int*   labels = (const int*)d_in[1];
    k_fused<<<128, 512>>>(emb, labels, (float*)d_out);
}